// round 7
// baseline (speedup 1.0000x reference)
#include <cuda_runtime.h>
#include <math.h>

// Causal attention: B=32, N=2048, D=128, fp32.
// Flash-attention, fp32 math via packed fma.rn.f32x2 (Blackwell FFMA2),
// 128x128 tiles, 256 threads, 8x8 microtile as 8x4 packed-pair accumulators.
// XOR-swizzled smem => conflict-free LDS.128 in both GEMM loops AND
// conflict-free STS.128 in the 4x4 register-block transpose loads.
// V tile loaded via cp.async, hidden behind stage-1 compute.
// exp() = poly exp2 on the FMA pipe (MUFU.EX2 rt=8 would cost ~= the GEMM).
// Per-SMSP model: GEMM 32k cyc/tile (FFMA2 rt=2, binding), softmax ~4%,
// exposed K-load ~2.5%. This design is at its scalar-pipe roofline.

#define NSEQ 2048
#define BATCH 32
#define DH 128
#define BM 128
#define BN 128
#define NTHREADS 256
#define SMEM_BYTES (3 * 128 * 128 * 4)

#define FMA_F32X2(d, a, b, c) \
    asm("fma.rn.f32x2 %0, %1, %2, %3;" : "=l"(d) : "l"(a), "l"(b), "l"(c))
#define MUL_F32X2_(d, a, b) \
    asm("mul.rn.f32x2 %0, %1, %2;" : "=l"(d) : "l"(a), "l"(b))
#define PACK2(d, x, y) \
    asm("mov.b64 %0, {%1, %2};" : "=l"(d) : "r"(__float_as_uint(x)), "r"(__float_as_uint(y)))
#define UNPACK2(lo, hi, v) \
    do { unsigned _ulo, _uhi; \
         asm("mov.b64 {%0, %1}, %2;" : "=r"(_ulo), "=r"(_uhi) : "l"(v)); \
         lo = __uint_as_float(_ulo); hi = __uint_as_float(_uhi); } while (0)

typedef unsigned long long u64;

// exp(x) for x <= 0 (incl. -inf), FMA/ALU pipes only.
// Magic-number round-to-nearest; f in [-0.5, 0.5]; degree-6 poly for 2^f
// (rel err < 3e-7); 2^round(y) via integer shift. No FRND/F2I, no MUFU.
// Clamp to -126 BEFORE rounding so -inf never produces NaN.
__device__ __forceinline__ float fast_exp_nonpos(float x)
{
    const float MAGIC = 12582912.0f;               // 1.5 * 2^23
    float y = fmaxf(x * 1.4426950408889634f, -126.0f);
    float t = y + MAGIC;
    int   r = __float_as_int(t) - __float_as_int(MAGIC);  // round(y), exact
    float f = y - (float)r;                        // [-0.5, 0.5]
    float p = 1.33988766e-4f;
    p = fmaf(p, f, 1.33308258e-3f);
    p = fmaf(p, f, 9.61838333e-3f);
    p = fmaf(p, f, 5.55036425e-2f);
    p = fmaf(p, f, 2.40226795e-1f);
    p = fmaf(p, f, 6.93147145e-1f);
    p = fmaf(p, f, 1.0f);
    float s = __int_as_float((r + 127) << 23);     // 2^r, r in [-126, 0]
    return p * s;
}

// Load a [128 rows][128 d] gmem tile into smem TRANSPOSED + swizzled:
//   smem word = d*128 + (row ^ (d & 28))
// 4x4 register-block transpose: LDG.128 coalesced, STS.128 conflict-free.
// Validity: key0 % 4 == 0 and sw bits live in [2..4], so
// (key0 + i) ^ sw == (key0 ^ sw) + i for i in 0..3 (float4 stays contiguous).
__device__ __forceinline__ void load_tile_T(const float* __restrict__ g,
                                            float* __restrict__ s_,
                                            int tid, float mul)
{
    const int key0  = (tid >> 3) * 4;   // 0..124, step 4
    const int lane8 = tid & 7;
    #pragma unroll
    for (int dblk = 0; dblk < 4; ++dblk) {
        int d4v = dblk * 8 + lane8;     // float4 column 0..31
        float4 r0 = *(const float4*)(g + (size_t)(key0 + 0) * DH + d4v * 4);
        float4 r1 = *(const float4*)(g + (size_t)(key0 + 1) * DH + d4v * 4);
        float4 r2 = *(const float4*)(g + (size_t)(key0 + 2) * DH + d4v * 4);
        float4 r3 = *(const float4*)(g + (size_t)(key0 + 3) * DH + d4v * 4);
        float a0[4] = {r0.x, r0.y, r0.z, r0.w};
        float a1[4] = {r1.x, r1.y, r1.z, r1.w};
        float a2[4] = {r2.x, r2.y, r2.z, r2.w};
        float a3[4] = {r3.x, r3.y, r3.z, r3.w};
        #pragma unroll
        for (int t = 0; t < 4; ++t) {
            int kk = 4 * d4v + t;
            int sw = kk & 28;
            float4 w;
            w.x = a0[t] * mul; w.y = a1[t] * mul;
            w.z = a2[t] * mul; w.w = a3[t] * mul;
            *(float4*)(s_ + (size_t)kk * BM + (key0 ^ sw)) = w;
        }
    }
}

__global__ void __launch_bounds__(NTHREADS, 1)
fa_fp32x2_kernel(const float* __restrict__ Q, const float* __restrict__ K,
                 const float* __restrict__ V, float* __restrict__ Out)
{
    extern __shared__ float smem[];
    float* Qs = smem;                // [d][row] transposed+swizzled
    float* Ks = smem + DH * BM;      // [d][key] transposed+swizzled (reused as Ps)
    float* Vs = smem + 2 * DH * BM;  // [key][d] natural

    const int tid = threadIdx.x;
    const int tx  = tid & 15;
    const int ty  = tid >> 4;
    // LPT schedule: heaviest q-tiles launch first.
    const int it  = (int)gridDim.x - 1 - (int)blockIdx.x;
    const int b   = blockIdx.y;
    const int m0  = it * BM;

    const float* Qb = Q + (size_t)b * NSEQ * DH;
    const float* Kb = K + (size_t)b * NSEQ * DH;
    const float* Vb = V + (size_t)b * NSEQ * DH;
    float*       Ob = Out + (size_t)b * NSEQ * DH;

    const float scale = 0.08838834764831845f;  // 1/sqrt(128)

    // ---- Q tile: transposed + swizzled + pre-scaled (once per CTA) ----
    load_tile_T(Qb + (size_t)m0 * DH, Qs, tid, scale);

    u64 o2[8][4];
    float m_i[8], l_i[8];
    const u64 zero2 = 0ull;
    #pragma unroll
    for (int i = 0; i < 8; ++i) {
        m_i[i] = -INFINITY;
        l_i[i] = 0.0f;
        #pragma unroll
        for (int j = 0; j < 4; ++j) o2[i][j] = zero2;
    }

    // Hoisted per-thread bases for the cp.async V loop (invariant across jt).
    const int vd4 = tid & 31;
    const int vr0 = tid >> 5;
    const unsigned vdst0 = (unsigned)__cvta_generic_to_shared(
        Vs + (size_t)vr0 * DH + vd4 * 4);
    const float* vsrc_b = Vb + (size_t)vr0 * DH + vd4 * 4;

    for (int jt = 0; jt <= it; ++jt) {
        const int n0 = jt * BN;

        // ---- (1) V tile via cp.async: issued first, waited just before stage 2 ----
        {
            const float* vsrc = vsrc_b + (size_t)n0 * DH;
            #pragma unroll
            for (int r = 0; r < 16; ++r) {
                asm volatile("cp.async.cg.shared.global [%0], [%1], 16;"
                             :: "r"(vdst0 + r * 8 * DH * 4),
                                "l"(vsrc + (size_t)r * 8 * DH));
            }
            asm volatile("cp.async.commit_group;");
        }

        // ---- (2) K tile: transposed + swizzled (overlaps in-flight V copies) ----
        load_tile_T(Kb + (size_t)n0 * DH, Ks, tid, 1.0f);
        __syncthreads();   // Ks (and first-iter Qs) visible; stage 1 never touches Vs

        // ---- Stage 1: S = Q * K^T (inner dim = D), packed FFMA2 ----
        u64 s2[8][4];
        #pragma unroll
        for (int i = 0; i < 8; ++i)
            #pragma unroll
            for (int j = 0; j < 4; ++j) s2[i][j] = zero2;

        #pragma unroll 4
        for (int kk = 0; kk < DH; ++kk) {
            const int sw = kk & 28;
            const float* qrow = Qs + kk * BM;
            const float* krow = Ks + kk * BN;
            float4 a0 = *(const float4*)(qrow + ((ty * 4) ^ sw));
            float4 a1 = *(const float4*)(qrow + 64 + ((ty * 4) ^ sw));
            ulonglong2 bq0 = *(const ulonglong2*)(krow + ((tx * 4) ^ sw));
            ulonglong2 bq1 = *(const ulonglong2*)(krow + 64 + ((tx * 4) ^ sw));
            u64 bP[4] = {bq0.x, bq0.y, bq1.x, bq1.y};
            float a[8] = {a0.x, a0.y, a0.z, a0.w, a1.x, a1.y, a1.z, a1.w};
            u64 aP[8];
            #pragma unroll
            for (int i = 0; i < 8; ++i) PACK2(aP[i], a[i], a[i]);
            #pragma unroll
            for (int i = 0; i < 8; ++i)
                #pragma unroll
                for (int j = 0; j < 4; ++j)
                    FMA_F32X2(s2[i][j], aP[i], bP[j], s2[i][j]);
        }

        float s_acc[8][8];
        #pragma unroll
        for (int i = 0; i < 8; ++i)
            #pragma unroll
            for (int j = 0; j < 4; ++j)
                UNPACK2(s_acc[i][2 * j], s_acc[i][2 * j + 1], s2[i][j]);

        // ---- Causal mask (diagonal tile only) ----
        if (jt == it) {
            #pragma unroll
            for (int i = 0; i < 8; ++i) {
                int r_i = ty * 4 + (i & 3) + ((i >> 2) << 6);
                #pragma unroll
                for (int j = 0; j < 8; ++j) {
                    int c_j = tx * 4 + (j & 3) + ((j >> 2) << 6);
                    if (c_j > r_i) s_acc[i][j] = -INFINITY;
                }
            }
        }

        // ---- Online softmax (width-16 shuffles; lanes with equal ty share rows) ----
        float mnew[8], alpha[8];
        #pragma unroll
        for (int i = 0; i < 8; ++i) {
            float mx = s_acc[i][0];
            #pragma unroll
            for (int j = 1; j < 8; ++j) mx = fmaxf(mx, s_acc[i][j]);
            #pragma unroll
            for (int off = 8; off > 0; off >>= 1)
                mx = fmaxf(mx, __shfl_xor_sync(0xffffffffu, mx, off, 16));
            mnew[i] = fmaxf(m_i[i], mx);
        }
        if (jt > 0) {
            #pragma unroll
            for (int i = 0; i < 8; ++i) {
                alpha[i] = fast_exp_nonpos(m_i[i] - mnew[i]);
                m_i[i]   = mnew[i];
            }
        } else {
            // First visited tile: o2 == 0 and l_i == 0; skip rescale work.
            #pragma unroll
            for (int i = 0; i < 8; ++i) { alpha[i] = 0.0f; m_i[i] = mnew[i]; }
        }

        #pragma unroll
        for (int i = 0; i < 8; ++i) {
            float srow = 0.0f;
            #pragma unroll
            for (int j = 0; j < 8; ++j) {
                float p = fast_exp_nonpos(s_acc[i][j] - mnew[i]);  // -inf -> ~0
                s_acc[i][j] = p;
                srow += p;
            }
            #pragma unroll
            for (int off = 8; off > 0; off >>= 1)
                srow += __shfl_xor_sync(0xffffffffu, srow, off, 16);
            l_i[i] = l_i[i] * alpha[i] + srow;
        }
        if (jt > 0) {
            #pragma unroll
            for (int i = 0; i < 8; ++i) {
                u64 aPk; PACK2(aPk, alpha[i], alpha[i]);
                #pragma unroll
                for (int j = 0; j < 4; ++j) MUL_F32X2_(o2[i][j], o2[i][j], aPk);
            }
        }

        __syncthreads();  // all stage-1 Ks reads complete before P overwrite

        // ---- Store P into Ps (= Ks buffer): word = key*128 + (row ^ (key&28)) ----
        float* Ps = Ks;
        #pragma unroll
        for (int jc = 0; jc < 2; ++jc) {
            #pragma unroll
            for (int jj = 0; jj < 4; ++jj) {
                int col = tx * 4 + jj + (jc << 6);
                int s   = col & 28;
                #pragma unroll
                for (int h = 0; h < 2; ++h) {
                    float4 v;
                    v.x = s_acc[h * 4 + 0][jc * 4 + jj];
                    v.y = s_acc[h * 4 + 1][jc * 4 + jj];
                    v.z = s_acc[h * 4 + 2][jc * 4 + jj];
                    v.w = s_acc[h * 4 + 3][jc * 4 + jj];
                    *(float4*)(Ps + col * BM + (h << 6) + ((ty * 4) ^ s)) = v;
                }
            }
        }

        // ---- V copies must be done before stage 2; barrier publishes P and V ----
        asm volatile("cp.async.wait_group 0;");
        __syncthreads();

        // ---- Stage 2: O += P * V (inner dim = key), packed FFMA2 ----
        #pragma unroll 4
        for (int kk = 0; kk < BN; ++kk) {
            const int sw = kk & 28;
            const float* prow = Ps + kk * BM;
            const float* vrow = Vs + kk * DH;
            float4 a0 = *(const float4*)(prow + ((ty * 4) ^ sw));
            float4 a1 = *(const float4*)(prow + 64 + ((ty * 4) ^ sw));
            ulonglong2 bq0 = *(const ulonglong2*)(vrow + tx * 4);
            ulonglong2 bq1 = *(const ulonglong2*)(vrow + 64 + tx * 4);
            u64 bP[4] = {bq0.x, bq0.y, bq1.x, bq1.y};
            float a[8] = {a0.x, a0.y, a0.z, a0.w, a1.x, a1.y, a1.z, a1.w};
            u64 aP[8];
            #pragma unroll
            for (int i = 0; i < 8; ++i) PACK2(aP[i], a[i], a[i]);
            #pragma unroll
            for (int i = 0; i < 8; ++i)
                #pragma unroll
                for (int j = 0; j < 4; ++j)
                    FMA_F32X2(o2[i][j], aP[i], bP[j], o2[i][j]);
        }
        __syncthreads();  // before next tile overwrites Ks / Vs
    }

    // ---- Epilogue: O / l, coalesced STG.128 ----
    #pragma unroll
    for (int i = 0; i < 8; ++i) {
        int row = m0 + ty * 4 + (i & 3) + ((i >> 2) << 6);
        float inv = 1.0f / l_i[i];
        float ov[8];
        #pragma unroll
        for (int j = 0; j < 4; ++j) UNPACK2(ov[2 * j], ov[2 * j + 1], o2[i][j]);
        float4 v0, v1;
        v0.x = ov[0] * inv; v0.y = ov[1] * inv;
        v0.z = ov[2] * inv; v0.w = ov[3] * inv;
        v1.x = ov[4] * inv; v1.y = ov[5] * inv;
        v1.z = ov[6] * inv; v1.w = ov[7] * inv;
        *(float4*)(Ob + (size_t)row * DH + tx * 4)      = v0;
        *(float4*)(Ob + (size_t)row * DH + 64 + tx * 4) = v1;
    }
}

extern "C" void kernel_launch(void* const* d_in, const int* in_sizes, int n_in,
                              void* d_out, int out_size)
{
    (void)in_sizes; (void)n_in; (void)out_size;
    const float* q = (const float*)d_in[0];
    const float* k = (const float*)d_in[1];
    const float* v = (const float*)d_in[2];
    float* out = (float*)d_out;

    cudaFuncSetAttribute(fa_fp32x2_kernel,
                         cudaFuncAttributeMaxDynamicSharedMemorySize, SMEM_BYTES);

    dim3 grid(NSEQ / BM, BATCH);
    fa_fp32x2_kernel<<<grid, NTHREADS, SMEM_BYTES>>>(q, k, v, out);
}